// round 16
// baseline (speedup 1.0000x reference)
#include <cuda_runtime.h>
#include <cuda_fp16.h>
#include <math.h>

// BilateralSlice: out[b,c,i,j] = trilinear(grid[b,c, h(j), w(i), d(guide[b,i,j])])
// Shapes: grid (4,12,16,16,8) f32, guide (4,1,1024,1024) f32, out (4,12,1024,1024) f32.
//
// R16 = R15 (two CTAs/row, 2 px/thread, fp16 w-lerped slab, all-half2 interp)
// with the slab split into two arrays so each corner is 1 LDS.128 + 1 LDS.64
// (8 loads/px instead of 12):
//   shA[h][d] : uint4  = channels 0..7  (16 B, 16-aligned)
//   shB[h][d] : uint2  = channels 8..11 (8 B)
// Index for both: h_local*9 + d  (d in 0..7, +1 pad slot per h).

#define CC   12
#define HG   16
#define DG   8
#define HH   1024
#define WW_  1024
#define NSLICE 9              // h-slices per half-row

__device__ __forceinline__ __half2 hlerp(__half2 a, __half2 b, __half2 f)
{   // a + f*(b-a)
    return __hfma2(__hsub2(b, a), f, a);
}

__global__ void __launch_bounds__(256, 4)
bslice_kernel(const float* __restrict__ grid,
              const float* __restrict__ guide,
              float* __restrict__ out)
{
    __shared__ uint4 shA[NSLICE * 9];      // [h][d] channels 0..7  (1296 B)
    __shared__ uint2 shB[NSLICE * 9];      // [h][d] channels 8..11 ( 648 B)
    __half* hA = (__half*)shA;             // half idx: h*72 + d*8 + c      (c<8)
    __half* hB = (__half*)shB;             // half idx: h*36 + d*4 + (c-8)

    const int half = blockIdx.x & 1;
    const int i    = blockIdx.x >> 1;      // image row
    const int b    = blockIdx.y;
    const int t    = threadIdx.x;
    const int hbase = half * 7;            // h-slices [hbase, hbase+8]

    // ---- w cell for this row (constant across the row) ----
    const float wwf = (float)i * (15.0f / 1023.0f);
    int w0 = (int)wwf; if (w0 > 15) w0 = 15;
    int w1 = w0 + 1;   if (w1 > 15) w1 = 15;
    const float fw = wwf - (float)w0;

    // ---- Stage w-interpolated slab (fp32 lerp, fp16 store): 216 groups ----
    const float4* g4 = (const float4*)grid;
    if (t < 216) {                         // 12c * 9h * 2 d-quads
        int c   = t / 18;
        int rem = t - c * 18;
        int h   = rem >> 1;
        int dq  = rem & 1;
        int base = ((b * CC + c) * HG + (hbase + h)) * 32;  // float4 off of [b,c,hg,0,0]
        float4 a  = g4[base + w0 * 2 + dq];
        float4 bb = g4[base + w1 * 2 + dq];
        float v0 = fmaf(fw, bb.x - a.x, a.x);
        float v1 = fmaf(fw, bb.y - a.y, a.y);
        float v2 = fmaf(fw, bb.z - a.z, a.z);
        float v3 = fmaf(fw, bb.w - a.w, a.w);
        int d0i = dq * 4;
        if (c < 8) {
            int o = h * 72 + d0i * 8 + c;
            hA[o]      = __float2half_rn(v0);
            hA[o + 8]  = __float2half_rn(v1);
            hA[o + 16] = __float2half_rn(v2);
            hA[o + 24] = __float2half_rn(v3);
        } else {
            int o = h * 36 + d0i * 4 + (c - 8);
            hB[o]      = __float2half_rn(v0);
            hB[o + 4]  = __float2half_rn(v1);
            hB[o + 8]  = __float2half_rn(v2);
            hB[o + 12] = __float2half_rn(v3);
        }
    }
    __syncthreads();

    // ---- Thread owns 2 consecutive columns ----
    const int j0 = half * 512 + t * 2;

    float2 gv = *(const float2*)(guide + ((size_t)b * HH + i) * WW_ + j0);
    float ga[2] = {gv.x, gv.y};

    float res[24];                         // res[c*2 + jj], constant indices only
    #pragma unroll
    for (int jj = 0; jj < 2; jj++) {
        float hhf = (float)(j0 + jj) * (15.0f / 1023.0f);
        int h0 = (int)hhf;
        int h1 = h0 + 1; if (h1 > 15) h1 = 15;
        const float fhj = hhf - (float)h0;
        const __half2 fh2 = __float2half2_rn(fhj);
        const int base0 = (h0 - hbase) * 9;
        const int base1 = (h1 - hbase) * 9;

        float dc  = ga[jj] * 7.0f;         // guide in [0,1) -> dc in [0,7)
        float dfl = floorf(dc);
        int d0 = (int)dfl;
        int d1 = d0 + 1; if (d1 > 7) d1 = 7;
        float dw = dc - dfl;
        const __half2 dw2 = __float2half2_rn(dw);

        // 4 corners: 1 LDS.128 + 1 LDS.64 each
        uint4 A00 = shA[base0 + d0];
        uint4 A01 = shA[base0 + d1];
        uint4 A10 = shA[base1 + d0];
        uint4 A11 = shA[base1 + d1];
        uint2 B00 = shB[base0 + d0];
        uint2 B01 = shB[base0 + d1];
        uint2 B10 = shB[base1 + d0];
        uint2 B11 = shB[base1 + d1];

        // d-lerp then h-blend, all half2; channel pairs in fixed lanes
        __half2 r0 = hlerp(hlerp(*(__half2*)&A00.x, *(__half2*)&A01.x, dw2),
                           hlerp(*(__half2*)&A10.x, *(__half2*)&A11.x, dw2), fh2);
        __half2 r1 = hlerp(hlerp(*(__half2*)&A00.y, *(__half2*)&A01.y, dw2),
                           hlerp(*(__half2*)&A10.y, *(__half2*)&A11.y, dw2), fh2);
        __half2 r2 = hlerp(hlerp(*(__half2*)&A00.z, *(__half2*)&A01.z, dw2),
                           hlerp(*(__half2*)&A10.z, *(__half2*)&A11.z, dw2), fh2);
        __half2 r3 = hlerp(hlerp(*(__half2*)&A00.w, *(__half2*)&A01.w, dw2),
                           hlerp(*(__half2*)&A10.w, *(__half2*)&A11.w, dw2), fh2);
        __half2 r4 = hlerp(hlerp(*(__half2*)&B00.x, *(__half2*)&B01.x, dw2),
                           hlerp(*(__half2*)&B10.x, *(__half2*)&B11.x, dw2), fh2);
        __half2 r5 = hlerp(hlerp(*(__half2*)&B00.y, *(__half2*)&B01.y, dw2),
                           hlerp(*(__half2*)&B10.y, *(__half2*)&B11.y, dw2), fh2);

        float2 f0 = __half22float2(r0);
        float2 f1 = __half22float2(r1);
        float2 f2 = __half22float2(r2);
        float2 f3 = __half22float2(r3);
        float2 f4 = __half22float2(r4);
        float2 f5 = __half22float2(r5);

        res[0  * 2 + jj] = f0.x;  res[1  * 2 + jj] = f0.y;
        res[2  * 2 + jj] = f1.x;  res[3  * 2 + jj] = f1.y;
        res[4  * 2 + jj] = f2.x;  res[5  * 2 + jj] = f2.y;
        res[6  * 2 + jj] = f3.x;  res[7  * 2 + jj] = f3.y;
        res[8  * 2 + jj] = f4.x;  res[9  * 2 + jj] = f4.y;
        res[10 * 2 + jj] = f5.x;  res[11 * 2 + jj] = f5.y;
    }

    // ---- Coalesced float2 stores: 12 channels ----
    #pragma unroll
    for (int c = 0; c < 12; c++) {
        float2 o = make_float2(res[c * 2 + 0], res[c * 2 + 1]);
        *(float2*)(out + (((size_t)b * CC + c) * HH + i) * WW_ + j0) = o;
    }
}

extern "C" void kernel_launch(void* const* d_in, const int* in_sizes, int n_in,
                              void* d_out, int out_size)
{
    const float* grid  = (const float*)d_in[0];
    const float* guide = (const float*)d_in[1];
    float* out = (float*)d_out;

    dim3 gr(HH * 2, 4);                    // two CTAs per (row, batch)
    bslice_kernel<<<gr, 256>>>(grid, guide, out);
}

// round 17
// speedup vs baseline: 1.3739x; 1.3739x over previous
#include <cuda_runtime.h>
#include <cuda_fp16.h>
#include <math.h>

// BilateralSlice: out[b,c,i,j] = trilinear(grid[b,c, h(j), w(i), d(guide[b,i,j])])
// Shapes: grid (4,12,16,16,8) f32, guide (4,1,1024,1024) f32, out (4,12,1024,1024) f32.
//
// R17 = R15 (two CTAs/row, 2 px/thread, fp16 w-lerped slab, half2 d-lerp +
// h-blend, 12 LDS.64 + 12 F2F per px) with:
//   - __launch_bounds__(256,5): 40 warps/SM (R15 regs=48 <= 51 cap)
//   - guide LDG hoisted above __syncthreads to overlap staging latency
// (R16's LDS.128 split-array layout regressed: same crossbar bytes, more alu.)

#define CC   12
#define HG   16
#define DG   8
#define HH   1024
#define WW_  1024

#define DSTRIDE_H 12          // halves per d
#define HSTRIDE_H 112         // halves per h (96 + 16 pad)
#define DSTRIDE_B 24          // bytes
#define HSTRIDE_B 224         // bytes
#define NSLICE    9           // h-slices per half-row

// d-lerp for two channel pairs packed in uint2 (4 channels): r = a0 + dw*(a1-a0)
__device__ __forceinline__ void dlerp2(uint2 u0, uint2 u1, __half2 dw2,
                                       __half2& r0, __half2& r1)
{
    __half2 a0 = *(const __half2*)&u0.x;
    __half2 a1 = *(const __half2*)&u1.x;
    r0 = __hfma2(__hsub2(a1, a0), dw2, a0);
    __half2 b0 = *(const __half2*)&u0.y;
    __half2 b1 = *(const __half2*)&u1.y;
    r1 = __hfma2(__hsub2(b1, b0), dw2, b0);
}

__global__ void __launch_bounds__(256, 5)
bslice_kernel(const float* __restrict__ grid,
              const float* __restrict__ guide,
              float* __restrict__ out)
{
    __shared__ __half sh[NSLICE * HSTRIDE_H];   // 1008 halves = 2016 B
    const char* sb = (const char*)sh;

    const int half = blockIdx.x & 1;
    const int i    = blockIdx.x >> 1;       // image row
    const int b    = blockIdx.y;
    const int t    = threadIdx.x;
    const int hbase = half * 7;             // h-slices [hbase, hbase+8]

    // ---- Guide load issued FIRST: overlaps staging + barrier latency ----
    const int j0 = half * 512 + t * 2;
    float2 gv = *(const float2*)(guide + ((size_t)b * HH + i) * WW_ + j0);

    // ---- w cell for this row (constant across the row) ----
    const float wwf = (float)i * (15.0f / 1023.0f);
    int w0 = (int)wwf; if (w0 > 15) w0 = 15;
    int w1 = w0 + 1;   if (w1 > 15) w1 = 15;
    const float fw = wwf - (float)w0;

    // ---- Stage w-interpolated slab (fp32 lerp, fp16 store): 216 groups ----
    const float4* g4 = (const float4*)grid;
    if (t < 216) {                          // 12c * 9h * 2 d-quads
        int c   = t / 18;
        int rem = t - c * 18;
        int h   = rem >> 1;
        int dq  = rem & 1;
        int base = ((b * CC + c) * HG + (hbase + h)) * 32;  // float4 off of [b,c,hg,0,0]
        float4 a  = g4[base + w0 * 2 + dq];
        float4 bb = g4[base + w1 * 2 + dq];
        int so = h * HSTRIDE_H + (dq * 4) * DSTRIDE_H + c;
        sh[so]                 = __float2half_rn(fmaf(fw, bb.x - a.x, a.x));
        sh[so + DSTRIDE_H]     = __float2half_rn(fmaf(fw, bb.y - a.y, a.y));
        sh[so + 2 * DSTRIDE_H] = __float2half_rn(fmaf(fw, bb.z - a.z, a.z));
        sh[so + 3 * DSTRIDE_H] = __float2half_rn(fmaf(fw, bb.w - a.w, a.w));
    }
    __syncthreads();

    float ga[2] = {gv.x, gv.y};

    float res[24];                          // res[c*2 + jj], constant indices only
    #pragma unroll
    for (int jj = 0; jj < 2; jj++) {
        float hhf = (float)(j0 + jj) * (15.0f / 1023.0f);
        int h0 = (int)hhf;
        int h1 = h0 + 1; if (h1 > 15) h1 = 15;
        const float fhj = hhf - (float)h0;
        const __half2 fh2 = __float2half2_rn(fhj);
        const int ho0 = (h0 - hbase) * HSTRIDE_B;
        const int ho1 = (h1 - hbase) * HSTRIDE_B;

        float dc  = ga[jj] * 7.0f;          // guide in [0,1) -> dc in [0,7)
        float dfl = floorf(dc);
        int d0 = (int)dfl;
        int d1 = d0 + 1; if (d1 > 7) d1 = 7;
        float dw = dc - dfl;
        const __half2 dw2 = __float2half2_rn(dw);

        const char* pA0 = sb + ho0 + d0 * DSTRIDE_B;   // (h0, d0)
        const char* pA1 = sb + ho0 + d1 * DSTRIDE_B;   // (h0, d1)
        const char* pB0 = sb + ho1 + d0 * DSTRIDE_B;   // (h1, d0)
        const char* pB1 = sb + ho1 + d1 * DSTRIDE_B;   // (h1, d1)

        #pragma unroll
        for (int qq = 0; qq < 3; qq++) {
            uint2 uA0 = *(const uint2*)(pA0 + 8 * qq);
            uint2 uA1 = *(const uint2*)(pA1 + 8 * qq);
            uint2 uB0 = *(const uint2*)(pB0 + 8 * qq);
            uint2 uB1 = *(const uint2*)(pB1 + 8 * qq);

            __half2 da0, da1, db0, db1;
            dlerp2(uA0, uA1, dw2, da0, da1);   // d-lerp at h0
            dlerp2(uB0, uB1, dw2, db0, db1);   // d-lerp at h1

            // h-blend in half2: r = da + fh*(db-da)
            __half2 hb0 = __hfma2(__hsub2(db0, da0), fh2, da0);
            __half2 hb1 = __hfma2(__hsub2(db1, da1), fh2, da1);

            float2 f0 = __half22float2(hb0);
            float2 f1 = __half22float2(hb1);

            const int c = qq * 4;
            res[(c + 0) * 2 + jj] = f0.x;
            res[(c + 1) * 2 + jj] = f0.y;
            res[(c + 2) * 2 + jj] = f1.x;
            res[(c + 3) * 2 + jj] = f1.y;
        }
    }

    // ---- Coalesced float2 stores: 12 channels ----
    #pragma unroll
    for (int c = 0; c < 12; c++) {
        float2 o = make_float2(res[c * 2 + 0], res[c * 2 + 1]);
        *(float2*)(out + (((size_t)b * CC + c) * HH + i) * WW_ + j0) = o;
    }
}

extern "C" void kernel_launch(void* const* d_in, const int* in_sizes, int n_in,
                              void* d_out, int out_size)
{
    const float* grid  = (const float*)d_in[0];
    const float* guide = (const float*)d_in[1];
    float* out = (float*)d_out;

    dim3 gr(HH * 2, 4);                     // two CTAs per (row, batch)
    bslice_kernel<<<gr, 256>>>(grid, guide, out);
}